// round 10
// baseline (speedup 1.0000x reference)
#include <cuda_runtime.h>
#include <cuda_fp16.h>
#include <cstdint>
#include <cstddef>

#define B_ROWS 8192
#define D_IN   1024
#define D_EMB  256
#define K_CENT 1024
#define WSUM   4849664

// ---------------- device scratch ----------------
__device__ __align__(16) __half g_xh[(size_t)B_ROWS * D_IN];
__device__ __align__(16) __half g_xl[(size_t)B_ROWS * D_IN];
__device__ __align__(16) __half g_h0h[(size_t)B_ROWS * 2048];
__device__ __align__(16) __half g_h0l[(size_t)B_ROWS * 2048];
__device__ __align__(16) __half g_h1h[(size_t)B_ROWS * 2048];
__device__ __align__(16) __half g_h1l[(size_t)B_ROWS * 2048];
__device__ __align__(16) __half g_eh[(size_t)B_ROWS * D_EMB];
__device__ __align__(16) __half g_el[(size_t)B_ROWS * D_EMB];
__device__ __align__(16) __half g_weh[WSUM];
__device__ __align__(16) __half g_wel[WSUM];
__device__ __align__(16) __half g_wd[WSUM];
__device__ __align__(16) __half g_ch[K_CENT * D_EMB];
__device__ __align__(16) __half g_cl[K_CENT * D_EMB];
__device__ __align__(16) float  g_S[(size_t)B_ROWS * K_CENT];
__device__ float g_c2[K_CENT];

// ---------------- helpers ----------------
__device__ __forceinline__ uint32_t smem_u32(const void* p) {
    uint32_t a;
    asm("{ .reg .u64 t; cvta.to.shared.u64 t, %1; cvt.u32.u64 %0, t; }" : "=r"(a) : "l"(p));
    return a;
}
__device__ __forceinline__ void split_fp16(float v, __half& h, __half& l) {
    h = __float2half_rn(v);
    l = __float2half_rn(v - __half2float(h));
}
__device__ __forceinline__ void mma_fp16(float* d, const uint32_t* a, const uint32_t* b) {
    asm volatile(
        "mma.sync.aligned.m16n8k16.row.col.f32.f16.f16.f32 "
        "{%0,%1,%2,%3}, {%4,%5,%6,%7}, {%8,%9}, {%0,%1,%2,%3};"
        : "+f"(d[0]), "+f"(d[1]), "+f"(d[2]), "+f"(d[3])
        : "r"(a[0]), "r"(a[1]), "r"(a[2]), "r"(a[3]), "r"(b[0]), "r"(b[1]));
}
#define LDSM_X4(r0, r1, r2, r3, addr) \
    asm volatile("ldmatrix.sync.aligned.m8n8.x4.shared.b16 {%0,%1,%2,%3}, [%4];" \
                 : "=r"(r0), "=r"(r1), "=r"(r2), "=r"(r3) : "r"(addr))
#define CP16(smaddr, gptr) \
    asm volatile("cp.async.cg.shared.global [%0], [%1], 16;" :: "r"(smaddr), "l"(gptr) : "memory")
#define CP_COMMIT() asm volatile("cp.async.commit_group;" ::: "memory")
#define CP_WAIT(n)  asm volatile("cp.async.wait_group %0;" :: "n"(n) : "memory")

// ===========================================================================
// Encoder GEMM: fp16x3 (hh+hl+lh), ldmatrix fragment loads, Kahan per 2 chunks.
// Tile 128x64, 8 warps (32x32), BK=32, 3 stages, 2 CTAs/SM.
// Stage bytes: Ah 10240 | Al 10240 | Bh 5120 | Bl 5120 = 30720 (rows 80 B).
// ===========================================================================
#define FP16E_SMEM (3 * 30720)

__global__ void __launch_bounds__(256, 2)
gemm_fp16e(const __half* __restrict__ Ah, const __half* __restrict__ Al,
           const __half* __restrict__ Bh, const __half* __restrict__ Bl,
           const float* __restrict__ bias,
           float* __restrict__ outF, __half* __restrict__ outH, __half* __restrict__ outL,
           int M, int N, int K, int doRelu)
{
    extern __shared__ __half smh[];
    const int tid  = threadIdx.x;
    const int lane = tid & 31, wid = tid >> 5;
    const int g = lane >> 2, q = lane & 3;
    const int warpM = (wid & 3) * 32, warpN = (wid >> 2) * 32;
    const int brow = blockIdx.y * 128, bcol = blockIdx.x * 64;
    const int nch = K >> 5;
    const uint32_t smb = smem_u32(smh);
    // ldmatrix per-lane byte offset within a tile: row = lane&15, colHalf = lane>>4
    const uint32_t laneOff = (uint32_t)((lane & 15) * 80 + (lane >> 4) * 16);

    float sum[2][4][4], comp[2][4][4], acc[2][4][4];
    #pragma unroll
    for (int i = 0; i < 2; i++)
        #pragma unroll
        for (int j = 0; j < 4; j++)
            #pragma unroll
            for (int r = 0; r < 4; r++) { sum[i][j][r] = 0.f; comp[i][j][r] = 0.f; acc[i][j][r] = 0.f; }

    const __half* gpA[2] = {Ah, Al};
    const __half* gpB[2] = {Bh, Bl};

    auto issue = [&](int ch, int s) {
        int kt = ch << 5;
        uint32_t sbase = smb + (uint32_t)s * 30720u;
        #pragma unroll
        for (int a = 0; a < 2; a++) {
            uint32_t base = sbase + (uint32_t)a * 10240u;
            #pragma unroll
            for (int it = 0; it < 2; it++) {
                int id = it * 256 + tid;
                int row = id >> 2, seg = id & 3;
                CP16(base + (uint32_t)(row * 80 + seg * 16),
                     gpA[a] + (size_t)(brow + row) * K + kt + seg * 8);
            }
        }
        #pragma unroll
        for (int a = 0; a < 2; a++) {
            uint32_t base = sbase + 20480u + (uint32_t)a * 5120u;
            int row = tid >> 2, seg = tid & 3;
            CP16(base + (uint32_t)(row * 80 + seg * 16),
                 gpB[a] + (size_t)(bcol + row) * K + kt + seg * 8);
        }
        CP_COMMIT();
    };

    issue(0, 0);
    if (nch > 1) issue(1, 1); else CP_COMMIT();
    if (nch > 2) issue(2, 2); else CP_COMMIT();

    for (int c = 0; c < nch; c++) {
        int s = c % 3;
        CP_WAIT(2);
        __syncthreads();

        uint32_t sbase = smb + (uint32_t)s * 30720u;
        uint32_t aAh = sbase + (uint32_t)(warpM * 80) + laneOff;
        uint32_t aAl = aAh + 10240u;
        uint32_t aBh = sbase + 20480u + (uint32_t)(warpN * 80) + laneOff;
        uint32_t aBl = aBh + 5120u;

        #pragma unroll
        for (int kb = 0; kb < 2; kb++) {          // kb*32 bytes = k offset 16
            uint32_t ko = (uint32_t)(kb * 32);
            uint32_t ah[2][4], al[2][4];
            #pragma unroll
            for (int i = 0; i < 2; i++) {
                LDSM_X4(ah[i][0], ah[i][1], ah[i][2], ah[i][3], aAh + ko + (uint32_t)(i * 16 * 80));
                LDSM_X4(al[i][0], al[i][1], al[i][2], al[i][3], aAl + ko + (uint32_t)(i * 16 * 80));
            }
            #pragma unroll
            for (int p = 0; p < 2; p++) {
                uint32_t bh4[4], bl4[4];
                LDSM_X4(bh4[0], bh4[1], bh4[2], bh4[3], aBh + ko + (uint32_t)(p * 16 * 80));
                LDSM_X4(bl4[0], bl4[1], bl4[2], bl4[3], aBl + ko + (uint32_t)(p * 16 * 80));
                #pragma unroll
                for (int jj = 0; jj < 2; jj++) {
                    int j = p * 2 + jj;
                    uint32_t bfh[2] = {bh4[jj], bh4[jj + 2]};
                    uint32_t bfl[2] = {bl4[jj], bl4[jj + 2]};
                    #pragma unroll
                    for (int i = 0; i < 2; i++) {
                        mma_fp16(acc[i][j], ah[i], bfh);
                        mma_fp16(acc[i][j], ah[i], bfl);
                        mma_fp16(acc[i][j], al[i], bfh);
                    }
                }
            }
        }

        if ((c & 1) || c == nch - 1) {
            #pragma unroll
            for (int i = 0; i < 2; i++)
                #pragma unroll
                for (int j = 0; j < 4; j++)
                    #pragma unroll
                    for (int r = 0; r < 4; r++) {
                        float v = acc[i][j][r];
                        float so = sum[i][j][r];
                        float t = so + v;
                        comp[i][j][r] += (so - t) + v;
                        sum[i][j][r] = t;
                        acc[i][j][r] = 0.f;
                    }
        }

        __syncthreads();
        if (c + 3 < nch) issue(c + 3, s); else CP_COMMIT();
    }

    #pragma unroll
    for (int i = 0; i < 2; i++) {
        int r0 = brow + warpM + i * 16 + g;
        #pragma unroll
        for (int j = 0; j < 4; j++) {
            int col = bcol + warpN + j * 8 + 2 * q;
            float b0 = 0.f, b1 = 0.f;
            if (bias) { b0 = __ldg(bias + col); b1 = __ldg(bias + col + 1); }
            float v00 = (sum[i][j][0] + comp[i][j][0]) + b0;
            float v01 = (sum[i][j][1] + comp[i][j][1]) + b1;
            float v10 = (sum[i][j][2] + comp[i][j][2]) + b0;
            float v11 = (sum[i][j][3] + comp[i][j][3]) + b1;
            if (doRelu) {
                v00 = fmaxf(v00, 0.f); v01 = fmaxf(v01, 0.f);
                v10 = fmaxf(v10, 0.f); v11 = fmaxf(v11, 0.f);
            }
            size_t o0 = (size_t)r0 * N + col, o1 = o0 + 8 * (size_t)N;
            if (outF) {
                *reinterpret_cast<float2*>(outF + o0) = make_float2(v00, v01);
                *reinterpret_cast<float2*>(outF + o1) = make_float2(v10, v11);
            }
            if (outH) {
                __half h[4], l[4];
                split_fp16(v00, h[0], l[0]); split_fp16(v01, h[1], l[1]);
                split_fp16(v10, h[2], l[2]); split_fp16(v11, h[3], l[3]);
                *reinterpret_cast<__half2*>(outH + o0) = __halves2half2(h[0], h[1]);
                *reinterpret_cast<__half2*>(outH + o1) = __halves2half2(h[2], h[3]);
                *reinterpret_cast<__half2*>(outL + o0) = __halves2half2(l[0], l[1]);
                *reinterpret_cast<__half2*>(outL + o1) = __halves2half2(l[2], l[3]);
            }
        }
    }
}

// ===========================================================================
// Decoder GEMM: fp16x2 asymmetric, ldmatrix loads.
// Stage bytes: Ah 10240 | Al 10240 | W 5120 = 25600.
// ===========================================================================
#define FP16D_SMEM (3 * 25600)

__global__ void __launch_bounds__(256, 2)
gemm_fp16d(const __half* __restrict__ Ah, const __half* __restrict__ Al,
           const __half* __restrict__ W,
           const float* __restrict__ bias,
           float* __restrict__ outF, __half* __restrict__ outH, __half* __restrict__ outL,
           int M, int N, int K, int doRelu)
{
    extern __shared__ __half smh[];
    const int tid  = threadIdx.x;
    const int lane = tid & 31, wid = tid >> 5;
    const int g = lane >> 2, q = lane & 3;
    const int warpM = (wid & 3) * 32, warpN = (wid >> 2) * 32;
    const int brow = blockIdx.y * 128, bcol = blockIdx.x * 64;
    const int nch = K >> 5;
    const uint32_t smb = smem_u32(smh);
    const uint32_t laneOff = (uint32_t)((lane & 15) * 80 + (lane >> 4) * 16);

    float acc[2][4][4];
    #pragma unroll
    for (int i = 0; i < 2; i++)
        #pragma unroll
        for (int j = 0; j < 4; j++)
            #pragma unroll
            for (int r = 0; r < 4; r++) acc[i][j][r] = 0.f;

    const __half* gpA[2] = {Ah, Al};

    auto issue = [&](int ch, int s) {
        int kt = ch << 5;
        uint32_t sbase = smb + (uint32_t)s * 25600u;
        #pragma unroll
        for (int a = 0; a < 2; a++) {
            uint32_t base = sbase + (uint32_t)a * 10240u;
            #pragma unroll
            for (int it = 0; it < 2; it++) {
                int id = it * 256 + tid;
                int row = id >> 2, seg = id & 3;
                CP16(base + (uint32_t)(row * 80 + seg * 16),
                     gpA[a] + (size_t)(brow + row) * K + kt + seg * 8);
            }
        }
        {
            uint32_t base = sbase + 20480u;
            int row = tid >> 2, seg = tid & 3;
            CP16(base + (uint32_t)(row * 80 + seg * 16),
                 W + (size_t)(bcol + row) * K + kt + seg * 8);
        }
        CP_COMMIT();
    };

    issue(0, 0);
    if (nch > 1) issue(1, 1); else CP_COMMIT();
    if (nch > 2) issue(2, 2); else CP_COMMIT();

    for (int c = 0; c < nch; c++) {
        int s = c % 3;
        CP_WAIT(2);
        __syncthreads();

        uint32_t sbase = smb + (uint32_t)s * 25600u;
        uint32_t aAh = sbase + (uint32_t)(warpM * 80) + laneOff;
        uint32_t aAl = aAh + 10240u;
        uint32_t aW  = sbase + 20480u + (uint32_t)(warpN * 80) + laneOff;

        #pragma unroll
        for (int kb = 0; kb < 2; kb++) {
            uint32_t ko = (uint32_t)(kb * 32);
            uint32_t ah[2][4], al[2][4];
            #pragma unroll
            for (int i = 0; i < 2; i++) {
                LDSM_X4(ah[i][0], ah[i][1], ah[i][2], ah[i][3], aAh + ko + (uint32_t)(i * 16 * 80));
                LDSM_X4(al[i][0], al[i][1], al[i][2], al[i][3], aAl + ko + (uint32_t)(i * 16 * 80));
            }
            #pragma unroll
            for (int p = 0; p < 2; p++) {
                uint32_t bw4[4];
                LDSM_X4(bw4[0], bw4[1], bw4[2], bw4[3], aW + ko + (uint32_t)(p * 16 * 80));
                #pragma unroll
                for (int jj = 0; jj < 2; jj++) {
                    int j = p * 2 + jj;
                    uint32_t bf[2] = {bw4[jj], bw4[jj + 2]};
                    #pragma unroll
                    for (int i = 0; i < 2; i++) {
                        mma_fp16(acc[i][j], ah[i], bf);
                        mma_fp16(acc[i][j], al[i], bf);
                    }
                }
            }
        }
        __syncthreads();
        if (c + 3 < nch) issue(c + 3, s); else CP_COMMIT();
    }

    #pragma unroll
    for (int i = 0; i < 2; i++) {
        int r0 = brow + warpM + i * 16 + g;
        #pragma unroll
        for (int j = 0; j < 4; j++) {
            int col = bcol + warpN + j * 8 + 2 * q;
            float b0 = 0.f, b1 = 0.f;
            if (bias) { b0 = __ldg(bias + col); b1 = __ldg(bias + col + 1); }
            float v00 = acc[i][j][0] + b0, v01 = acc[i][j][1] + b1;
            float v10 = acc[i][j][2] + b0, v11 = acc[i][j][3] + b1;
            if (doRelu) {
                v00 = fmaxf(v00, 0.f); v01 = fmaxf(v01, 0.f);
                v10 = fmaxf(v10, 0.f); v11 = fmaxf(v11, 0.f);
            }
            size_t o0 = (size_t)r0 * N + col, o1 = o0 + 8 * (size_t)N;
            if (outF) {
                *reinterpret_cast<float2*>(outF + o0) = make_float2(v00, v01);
                *reinterpret_cast<float2*>(outF + o1) = make_float2(v10, v11);
            }
            if (outH) {
                __half h[4], l[4];
                split_fp16(v00, h[0], l[0]); split_fp16(v01, h[1], l[1]);
                split_fp16(v10, h[2], l[2]); split_fp16(v11, h[3], l[3]);
                *reinterpret_cast<__half2*>(outH + o0) = __halves2half2(h[0], h[1]);
                *reinterpret_cast<__half2*>(outH + o1) = __halves2half2(h[2], h[3]);
                *reinterpret_cast<__half2*>(outL + o0) = __halves2half2(l[0], l[1]);
                *reinterpret_cast<__half2*>(outL + o1) = __halves2half2(l[2], l[3]);
            }
        }
    }
}

// ---------------- prep kernels ----------------
__global__ void vec_split_fp16(const float* __restrict__ a,
                               __half* __restrict__ hi, __half* __restrict__ lo, int n2)
{
    int i = blockIdx.x * blockDim.x + threadIdx.x;
    if (i >= n2) return;
    float2 v = reinterpret_cast<const float2*>(a)[i];
    __half hx, lx, hy, ly;
    split_fp16(v.x, hx, lx); split_fp16(v.y, hy, ly);
    reinterpret_cast<__half2*>(hi)[i] = __halves2half2(hx, hy);
    reinterpret_cast<__half2*>(lo)[i] = __halves2half2(lx, ly);
}

__global__ void wt_split_fp16(const float* __restrict__ W, __half* __restrict__ hi,
                              __half* __restrict__ lo, int Kd, int N)
{
    __shared__ float t[32][33];
    int bx = blockIdx.x * 32, by = blockIdx.y * 32;
    for (int i = threadIdx.y; i < 32; i += 8)
        t[i][threadIdx.x] = W[(size_t)(by + i) * N + bx + threadIdx.x];
    __syncthreads();
    for (int i = threadIdx.y; i < 32; i += 8) {
        float v = t[threadIdx.x][i];
        __half h, l;
        split_fp16(v, h, l);
        size_t o = (size_t)(bx + i) * Kd + by + threadIdx.x;
        hi[o] = h; lo[o] = l;
    }
}

__global__ void wt_single_fp16(const float* __restrict__ W, __half* __restrict__ out,
                               int Kd, int N)
{
    __shared__ float t[32][33];
    int bx = blockIdx.x * 32, by = blockIdx.y * 32;
    for (int i = threadIdx.y; i < 32; i += 8)
        t[i][threadIdx.x] = W[(size_t)(by + i) * N + bx + threadIdx.x];
    __syncthreads();
    for (int i = threadIdx.y; i < 32; i += 8)
        out[(size_t)(bx + i) * Kd + by + threadIdx.x] = __float2half_rn(t[threadIdx.x][i]);
}

__global__ void c2_kernel(const float* __restrict__ c, float* __restrict__ c2)
{
    int k = blockIdx.x * 8 + (threadIdx.x >> 5);
    int lane = threadIdx.x & 31;
    float s = 0.0f;
    for (int d = lane; d < D_EMB; d += 32) {
        float v = c[(size_t)k * D_EMB + d];
        s = fmaf(v, v, s);
    }
    #pragma unroll
    for (int o = 16; o; o >>= 1) s += __shfl_xor_sync(0xFFFFFFFFu, s, o);
    if (lane == 0) c2[k] = s;
}

__global__ void argmin_labels(const float* __restrict__ emb, const float* __restrict__ S,
                              const float* __restrict__ c2, float* __restrict__ labels)
{
    const int row = blockIdx.x, tid = threadIdx.x;
    __shared__ float red[256];
    float v = emb[(size_t)row * D_EMB + tid];
    red[tid] = v * v;
    __syncthreads();
    #pragma unroll
    for (int s = 128; s > 0; s >>= 1) {
        if (tid < s) red[tid] += red[tid + s];
        __syncthreads();
    }
    const float e2 = red[0];
    __syncthreads();
    float best = 3.402823466e38f;
    int bi = 0;
    for (int k = tid; k < K_CENT; k += 256) {
        float d = fmaxf(e2 + c2[k] - 2.0f * S[(size_t)row * K_CENT + k], 0.0f);
        if (d < best) { best = d; bi = k; }
    }
    __shared__ float sv[256];
    __shared__ int si[256];
    sv[tid] = best; si[tid] = bi;
    __syncthreads();
    #pragma unroll
    for (int s = 128; s > 0; s >>= 1) {
        if (tid < s) {
            float v2 = sv[tid + s]; int i2 = si[tid + s];
            if (v2 < sv[tid] || (v2 == sv[tid] && i2 < si[tid])) { sv[tid] = v2; si[tid] = i2; }
        }
        __syncthreads();
    }
    const int win = si[0];
    for (int k = tid; k < K_CENT; k += 256)
        labels[(size_t)row * K_CENT + k] = (k == win) ? 1.0f : 0.0f;
}

// ---------------- host launcher ----------------
extern "C" void kernel_launch(void* const* d_in, const int* in_sizes, int n_in,
                              void* d_out, int out_size)
{
    (void)in_sizes; (void)n_in; (void)out_size;

    cudaFuncSetAttribute(gemm_fp16e, cudaFuncAttributeMaxDynamicSharedMemorySize, FP16E_SMEM);
    cudaFuncSetAttribute(gemm_fp16d, cudaFuncAttributeMaxDynamicSharedMemorySize, FP16D_SMEM);

    const float* x = (const float*)d_in[0];
    const float* W[8]  = {(const float*)d_in[1],  (const float*)d_in[3],
                          (const float*)d_in[5],  (const float*)d_in[7],
                          (const float*)d_in[9],  (const float*)d_in[11],
                          (const float*)d_in[13], (const float*)d_in[15]};
    const float* bv[8] = {(const float*)d_in[2],  (const float*)d_in[4],
                          (const float*)d_in[6],  (const float*)d_in[8],
                          (const float*)d_in[10], (const float*)d_in[12],
                          (const float*)d_in[14], (const float*)d_in[16]};
    const float* centers = (const float*)d_in[17];

    float* out    = (float*)d_out;
    float* recon  = out;
    float* emb    = out + (size_t)B_ROWS * D_IN;
    float* labels = emb + (size_t)B_ROWS * D_EMB;

    __half *xh, *xl, *h0h, *h0l, *h1h, *h1l, *eh, *el, *weh, *wel, *wd, *ch, *cl;
    float *S, *c2;
    cudaGetSymbolAddress((void**)&xh, g_xh);   cudaGetSymbolAddress((void**)&xl, g_xl);
    cudaGetSymbolAddress((void**)&h0h, g_h0h); cudaGetSymbolAddress((void**)&h0l, g_h0l);
    cudaGetSymbolAddress((void**)&h1h, g_h1h); cudaGetSymbolAddress((void**)&h1l, g_h1l);
    cudaGetSymbolAddress((void**)&eh, g_eh);   cudaGetSymbolAddress((void**)&el, g_el);
    cudaGetSymbolAddress((void**)&weh, g_weh); cudaGetSymbolAddress((void**)&wel, g_wel);
    cudaGetSymbolAddress((void**)&wd, g_wd);
    cudaGetSymbolAddress((void**)&ch, g_ch);   cudaGetSymbolAddress((void**)&cl, g_cl);
    cudaGetSymbolAddress((void**)&S, g_S);     cudaGetSymbolAddress((void**)&c2, g_c2);

    const int fi[8] = {1024, 2048, 1024, 512, 256, 512, 1024, 2048};
    const int fo[8] = {2048, 1024, 512, 256, 512, 1024, 2048, 1024};
    size_t off[8], acc = 0, accd = 0;
    for (int i = 0; i < 4; i++) { off[i] = acc;  acc  += (size_t)fi[i] * fo[i]; }
    for (int i = 4; i < 8; i++) { off[i] = accd; accd += (size_t)fi[i] * fo[i]; }

    auto wenc = [&](int i) {
        dim3 g(fo[i] / 32, fi[i] / 32), b(32, 8);
        wt_split_fp16<<<g, b>>>(W[i], weh + off[i], wel + off[i], fi[i], fo[i]);
    };

    c2_kernel<<<K_CENT / 8, 256>>>(centers, c2);                               // 1
    vec_split_fp16<<<(B_ROWS * D_IN / 2 + 255) / 256, 256>>>(x, xh, xl,
                                                             B_ROWS * D_IN / 2); // 2
    wenc(0);                                                                   // 3
    {
        dim3 g0(2048 / 64, B_ROWS / 128);                                      // 4
        gemm_fp16e<<<g0, 256, FP16E_SMEM>>>(xh, xl, weh + off[0], wel + off[0], bv[0],
                                            nullptr, h0h, h0l, B_ROWS, 2048, 1024, 1);
    }
    wenc(1);                                                                   // 5
    {
        dim3 g1(1024 / 64, B_ROWS / 128);                                      // 6
        gemm_fp16e<<<g1, 256, FP16E_SMEM>>>(h0h, h0l, weh + off[1], wel + off[1], bv[1],
                                            nullptr, h1h, h1l, B_ROWS, 1024, 2048, 1);
    }
    wenc(2);
    {
        dim3 g2(512 / 64, B_ROWS / 128);
        gemm_fp16e<<<g2, 256, FP16E_SMEM>>>(h1h, h1l, weh + off[2], wel + off[2], bv[2],
                                            nullptr, h0h, h0l, B_ROWS, 512, 1024, 1);
    }
    wenc(3);
    {
        dim3 g3(256 / 64, B_ROWS / 128);
        gemm_fp16e<<<g3, 256, FP16E_SMEM>>>(h0h, h0l, weh + off[3], wel + off[3], bv[3],
                                            emb, eh, el, B_ROWS, 256, 512, 0);
    }

    vec_split_fp16<<<(K_CENT * D_EMB / 2 + 255) / 256, 256>>>(centers, ch, cl,
                                                              K_CENT * D_EMB / 2);
    {
        dim3 g(K_CENT / 64, B_ROWS / 128);
        gemm_fp16e<<<g, 256, FP16E_SMEM>>>(eh, el, ch, cl, nullptr,
                                           S, nullptr, nullptr, B_ROWS, K_CENT, D_EMB, 0);
    }
    argmin_labels<<<B_ROWS, 256>>>(emb, S, c2, labels);

    for (int i = 4; i < 8; i++) {
        dim3 g(fo[i] / 32, fi[i] / 32), b(32, 8);
        wt_single_fp16<<<g, b>>>(W[i], wd + off[i], fi[i], fo[i]);
    }
    {
        dim3 g0(512 / 64, B_ROWS / 128);
        gemm_fp16d<<<g0, 256, FP16D_SMEM>>>(eh, el, wd + off[4], bv[4],
                                            nullptr, h0h, h0l, B_ROWS, 512, 256, 1);
        dim3 g1(1024 / 64, B_ROWS / 128);
        gemm_fp16d<<<g1, 256, FP16D_SMEM>>>(h0h, h0l, wd + off[5], bv[5],
                                            nullptr, h1h, h1l, B_ROWS, 1024, 512, 1);
        dim3 g2(2048 / 64, B_ROWS / 128);
        gemm_fp16d<<<g2, 256, FP16D_SMEM>>>(h1h, h1l, wd + off[6], bv[6],
                                            nullptr, h0h, h0l, B_ROWS, 2048, 1024, 1);
        dim3 g3(1024 / 64, B_ROWS / 128);
        gemm_fp16d<<<g3, 256, FP16D_SMEM>>>(h0h, h0l, wd + off[7], bv[7],
                                            recon, nullptr, nullptr, B_ROWS, 1024, 2048, 0);
    }
}